// round 9
// baseline (speedup 1.0000x reference)
#include <cuda_runtime.h>
#include <cuda_bf16.h>
#include <cstdint>
#include <cstddef>

#define BATCH 4
#define CC    512
#define OO    64
#define NN    4096

// ---------------- scratch (device globals; allocation-free) ----------------
__device__ __nv_bfloat16 d_xT [BATCH * NN * CC];      // x transposed [b][n][k] bf16
__device__ __nv_bfloat16 d_fgw[256 * CC];             // stacked [f_w; g_w] bf16, padded to 256 rows
__device__ __nv_bfloat16 d_hw [CC * CC];              // h_w bf16
__device__ __nv_bfloat16 d_fT [BATCH * NN * OO];      // f transposed [b][i][o]
__device__ __nv_bfloat16 d_gT [BATCH * NN * OO];      // g transposed [b][j][o]
__device__ __nv_bfloat16 d_hB [BATCH * CC * NN];      // h bf16 [b][c][n]
__device__ __nv_bfloat16 d_eT [(size_t)BATCH * NN * NN]; // exp(scores)^T [b][m][n] bf16
__device__ float d_colsum[BATCH * NN];                // sum_n exp(scores[n][m])

// ------------------------- helpers -----------------------------------------
__device__ __forceinline__ uint32_t smem_u32(const void* p) {
    uint32_t a;
    asm("{ .reg .u64 t; cvta.to.shared.u64 t, %1; cvt.u32.u64 %0, t; }"
        : "=r"(a) : "l"(p));
    return a;
}
__device__ __forceinline__ void cpa16(uint32_t s, const void* g) {
    asm volatile("cp.async.cg.shared.global [%0], [%1], 16;" :: "r"(s), "l"(g));
}
#define CP_COMMIT() asm volatile("cp.async.commit_group;" ::: "memory")
#define CP_WAIT1()  asm volatile("cp.async.wait_group 1;" ::: "memory")

__device__ __forceinline__ void ldmx4(uint32_t& r0, uint32_t& r1, uint32_t& r2,
                                      uint32_t& r3, uint32_t addr) {
    asm volatile("ldmatrix.sync.aligned.m8n8.x4.shared.b16 {%0,%1,%2,%3}, [%4];"
                 : "=r"(r0), "=r"(r1), "=r"(r2), "=r"(r3) : "r"(addr));
}
__device__ __forceinline__ void mma16816(float c[4], const uint32_t a[4],
                                         const uint32_t b[2]) {
    asm volatile(
        "mma.sync.aligned.m16n8k16.row.col.f32.bf16.bf16.f32 "
        "{%0,%1,%2,%3}, {%4,%5,%6,%7}, {%8,%9}, {%0,%1,%2,%3};"
        : "+f"(c[0]), "+f"(c[1]), "+f"(c[2]), "+f"(c[3])
        : "r"(a[0]), "r"(a[1]), "r"(a[2]), "r"(a[3]), "r"(b[0]), "r"(b[1]));
}

// Block tile: 256(M) x 128(N) x 32(K). 8 warps of 64x64. 256 threads.
// smem rows pitch 40 bf16 (80B). A tile 256x32, B tile 128x32.
#define TPITCH 40
#define ABYTES (256 * TPITCH * 2)          // 20480
#define BBYTES (128 * TPITCH * 2)          // 10240
#define STAGE_BYTES (ABYTES + BBYTES)      // 30720
#define NSTAGE 3
#define SMEM_DYN (NSTAGE * STAGE_BYTES)    // 92160

// Core GEMM: acc[mt][nt][4] += A[256 x K] * B[128 x K]^T, both K-major.
// 3-stage cp.async circular pipeline, ONE __syncthreads per chunk.
__device__ __forceinline__ void gemm_core(
    const __nv_bfloat16* __restrict__ A, int lda,
    const __nv_bfloat16* __restrict__ B, int ldb,
    int nk, float acc[4][8][4], char* smem)
{
    const int tid = threadIdx.x;
    const int lane = tid & 31, wid = tid >> 5;
    const int wm = (wid & 3) * 64, wn = (wid >> 2) * 64;
    const uint32_t sbase = smem_u32(smem);

    auto issue = [&](int st) {
        if (st < nk) {
            uint32_t sA = sbase + (st % NSTAGE) * STAGE_BYTES;
            uint32_t sB = sA + ABYTES;
            #pragma unroll
            for (int p = 0; p < 6; p++) {
                int idx = tid + p * 256;           // 0..1535
                if (idx < 1024) {                  // A: 256 rows x 4 chunks
                    int row = idx >> 2, c = idx & 3;
                    cpa16(sA + (row * TPITCH + c * 8) * 2,
                          A + (size_t)row * lda + st * 32 + c * 8);
                } else {                           // B: 128 rows x 4 chunks
                    int i2 = idx - 1024;
                    int row = i2 >> 2, c = i2 & 3;
                    cpa16(sB + (row * TPITCH + c * 8) * 2,
                          B + (size_t)row * ldb + st * 32 + c * 8);
                }
            }
        }
        CP_COMMIT();
    };

    issue(0); issue(1);
    for (int k0 = 0; k0 < nk; k0++) {
        CP_WAIT1();
        __syncthreads();
        issue(k0 + 2);

        uint32_t sA = sbase + (k0 % NSTAGE) * STAGE_BYTES;
        uint32_t sB = sA + ABYTES;
        #pragma unroll
        for (int ks = 0; ks < 2; ks++) {
            uint32_t afr[4][4];
            #pragma unroll
            for (int mt = 0; mt < 4; mt++) {
                int row = wm + mt * 16 + (lane & 15);
                int col = ks * 16 + ((lane >> 4) & 1) * 8;
                ldmx4(afr[mt][0], afr[mt][1], afr[mt][2], afr[mt][3],
                      sA + (row * TPITCH + col) * 2);
            }
            uint32_t bfr[8][2];
            #pragma unroll
            for (int np = 0; np < 4; np++) {
                int row = wn + np * 16 + (lane & 7) + ((lane >> 4) & 1) * 8;
                int col = ks * 16 + ((lane >> 3) & 1) * 8;
                uint32_t r0, r1, r2, r3;
                ldmx4(r0, r1, r2, r3, sB + (row * TPITCH + col) * 2);
                bfr[np * 2][0] = r0; bfr[np * 2][1] = r1;
                bfr[np * 2 + 1][0] = r2; bfr[np * 2 + 1][1] = r3;
            }
            #pragma unroll
            for (int mt = 0; mt < 4; mt++)
                #pragma unroll
                for (int nt = 0; nt < 8; nt++)
                    mma16816(acc[mt][nt], afr[mt], bfr[nt]);
        }
    }
}

// ---------------------------------------------------------------------------
// prep: convert weights to bf16 (stacked fg padded to 256 + h) + zero colsum
// ---------------------------------------------------------------------------
__global__ __launch_bounds__(256)
void conv_w_kernel(const float* __restrict__ fw, const float* __restrict__ gw,
                   const float* __restrict__ hw,
                   __nv_bfloat16* __restrict__ fgw, __nv_bfloat16* __restrict__ hwb,
                   float* __restrict__ colsum)
{
    int i = blockIdx.x * 256 + threadIdx.x;
    if (i < BATCH * NN) colsum[i] = 0.0f;
    if (i < 128 * CC) {
        float v = (i < 64 * CC) ? fw[i] : gw[i - 64 * CC];
        fgw[i] = __float2bfloat16(v);
    } else if (i < 256 * CC) {
        fgw[i] = __float2bfloat16(0.0f);   // pad rows 128..255
    }
    int j = i - 256 * CC;
    if (j >= 0 && j < CC * CC) hwb[j] = __float2bfloat16(hw[j]);
}

// ---------------------------------------------------------------------------
// prep: transpose x [b][k][n] fp32 -> xT [b][n][k] bf16
// ---------------------------------------------------------------------------
__global__ __launch_bounds__(256)
void transpose_x_kernel(const float* __restrict__ x, __nv_bfloat16* __restrict__ xT)
{
    __shared__ float t[32][33];
    const int b = blockIdx.z;
    const int n0 = blockIdx.x * 32, k0 = blockIdx.y * 32;
    const float* xb = x + (size_t)b * CC * NN;
    for (int r = threadIdx.y; r < 32; r += 8)
        t[r][threadIdx.x] = xb[(size_t)(k0 + r) * NN + n0 + threadIdx.x];
    __syncthreads();
    __nv_bfloat16* xo = xT + (size_t)b * NN * CC;
    for (int r = threadIdx.y; r < 32; r += 8)
        xo[(size_t)(n0 + r) * CC + k0 + threadIdx.x] = __float2bfloat16(t[threadIdx.x][r]);
}

// ---------------------------------------------------------------------------
// fg projection: A = fgw (padded 256 rows, o stacked), B = xT tile -> fT/gT [n][o]
// grid: (NN/128, 1, BATCH)
// ---------------------------------------------------------------------------
__global__ __launch_bounds__(256, 1)
void fg_proj_mma(const __nv_bfloat16* __restrict__ fgw, const __nv_bfloat16* __restrict__ xT,
                 const float* __restrict__ f_b, const float* __restrict__ g_b,
                 __nv_bfloat16* __restrict__ fT, __nv_bfloat16* __restrict__ gT)
{
    extern __shared__ char dsm[];
    const int b = blockIdx.z, n0 = blockIdx.x * 128;
    const int lane = threadIdx.x & 31, wid = threadIdx.x >> 5;
    const int wm = (wid & 3) * 64, wn = (wid >> 2) * 64;

    float acc[4][8][4] = {};
    gemm_core(fgw, CC, xT + (size_t)(b * NN + n0) * CC, CC, CC / 32, acc, dsm);

    __nv_bfloat16* fTb = fT + (size_t)b * NN * OO;
    __nv_bfloat16* gTb = gT + (size_t)b * NN * OO;
    #pragma unroll
    for (int mt = 0; mt < 4; mt++) {
        #pragma unroll
        for (int half = 0; half < 2; half++) {
            int o = wm + mt * 16 + (lane >> 2) + half * 8;
            if (o < 128) {
                float bias = (o < 64) ? f_b[o] : g_b[o - 64];
                __nv_bfloat16* dst = (o < 64) ? (fTb + o) : (gTb + (o - 64));
                #pragma unroll
                for (int nt = 0; nt < 8; nt++) {
                    int n = n0 + wn + nt * 8 + (lane & 3) * 2;
                    dst[(size_t)n * OO]       = __float2bfloat16(acc[mt][nt][half * 2]     + bias);
                    dst[(size_t)(n + 1) * OO] = __float2bfloat16(acc[mt][nt][half * 2 + 1] + bias);
                }
            }
        }
    }
}

// ---------------------------------------------------------------------------
// h projection: D[c(256)][n(128)] over K=512; write hB [c][n] bf16
// grid: (NN/128, CC/256, BATCH)
// ---------------------------------------------------------------------------
__global__ __launch_bounds__(256, 1)
void h_proj_mma(const __nv_bfloat16* __restrict__ hwb, const __nv_bfloat16* __restrict__ xT,
                const float* __restrict__ h_b, __nv_bfloat16* __restrict__ hB)
{
    extern __shared__ char dsm[];
    const int b = blockIdx.z, c0 = blockIdx.y * 256, n0 = blockIdx.x * 128;
    const int lane = threadIdx.x & 31, wid = threadIdx.x >> 5;
    const int wm = (wid & 3) * 64, wn = (wid >> 2) * 64;

    float acc[4][8][4] = {};
    gemm_core(hwb + (size_t)c0 * CC, CC,
              xT + (size_t)(b * NN + n0) * CC, CC, CC / 32, acc, dsm);

    __nv_bfloat16* hb = hB + (size_t)b * CC * NN;
    #pragma unroll
    for (int mt = 0; mt < 4; mt++) {
        #pragma unroll
        for (int half = 0; half < 2; half++) {
            int c = c0 + wm + mt * 16 + (lane >> 2) + half * 8;
            float bias = h_b[c];
            #pragma unroll
            for (int nt = 0; nt < 8; nt++) {
                int n = n0 + wn + nt * 8 + (lane & 3) * 2;
                __nv_bfloat162 v;
                v.x = __float2bfloat16(acc[mt][nt][half * 2]     + bias);
                v.y = __float2bfloat16(acc[mt][nt][half * 2 + 1] + bias);
                *(__nv_bfloat162*)(hb + (size_t)c * NN + n) = v;
            }
        }
    }
}

// ---------------------------------------------------------------------------
// scores+exp+transpose: e[i][j] = exp(fT[i,:].gT[j,:]); i-tile 256, j-tile 128.
// Writes eT[j][i] bf16; atomically accumulates colsum[j].
// grid: (NN/128 [j], NN/256 [i], BATCH)
// ---------------------------------------------------------------------------
#define SPITCH 264   // bf16 elems per smem row for 256 i-cols (528B, 16B aligned)

__global__ __launch_bounds__(256, 1)
void scores_mma(const __nv_bfloat16* __restrict__ fT, const __nv_bfloat16* __restrict__ gT,
                __nv_bfloat16* __restrict__ eT, float* __restrict__ colsum)
{
    extern __shared__ char dsm[];
    const int b = blockIdx.z, i0 = blockIdx.y * 256, j0 = blockIdx.x * 128;
    const int tid = threadIdx.x;
    const int lane = tid & 31, wid = tid >> 5;
    const int wm = (wid & 3) * 64, wn = (wid >> 2) * 64;

    float acc[4][8][4] = {};
    gemm_core(fT + (size_t)(b * NN + i0) * OO, OO,
              gT + (size_t)(b * NN + j0) * OO, OO, OO / 32, acc, dsm);

    __syncthreads();   // done with pipeline smem; reuse as transpose buffer
    __nv_bfloat16* ts = (__nv_bfloat16*)dsm;   // [128 j][SPITCH] (256 i used)

    // exp + transposed store into smem: ts[j][i] = bf16(exp(score[i][j]))
    #pragma unroll
    for (int mt = 0; mt < 4; mt++) {
        #pragma unroll
        for (int half = 0; half < 2; half++) {
            int i = wm + mt * 16 + (lane >> 2) + half * 8;
            #pragma unroll
            for (int nt = 0; nt < 8; nt++) {
                int j = wn + nt * 8 + (lane & 3) * 2;
                ts[(size_t)j * SPITCH + i]       =
                    __float2bfloat16(__expf(acc[mt][nt][half * 2]));
                ts[(size_t)(j + 1) * SPITCH + i] =
                    __float2bfloat16(__expf(acc[mt][nt][half * 2 + 1]));
            }
        }
    }
    __syncthreads();

    // coalesced write: eT[b][j0+j][i0 .. i0+255], 128 rows x 32 uint4
    __nv_bfloat16* eb = eT + (size_t)b * NN * NN + (size_t)j0 * NN + i0;
    #pragma unroll
    for (int p = 0; p < 16; p++) {
        int lin = tid + p * 256;
        int row = lin >> 5, u = lin & 31;
        uint4 v = *(const uint4*)(ts + (size_t)row * SPITCH + u * 8);
        *(uint4*)(eb + (size_t)row * NN + u * 8) = v;
    }

    // partial column sums: thread pair (j, half) sums 128 values each
    {
        int j = tid >> 1, hf = tid & 1;
        const __nv_bfloat16* rowp = ts + (size_t)j * SPITCH + hf * 128;
        float s = 0.0f;
        #pragma unroll
        for (int u = 0; u < 16; u++) {
            uint4 v = *(const uint4*)(rowp + u * 8);
            const __nv_bfloat162* h2 = (const __nv_bfloat162*)&v;
            #pragma unroll
            for (int q = 0; q < 4; q++) {
                float2 f2 = __bfloat1622float2(h2[q]);
                s += f2.x + f2.y;
            }
        }
        s += __shfl_xor_sync(0xffffffff, s, 1);
        if (hf == 0) atomicAdd(&colsum[b * NN + j0 + j], s);
    }
}

// ---------------------------------------------------------------------------
// attn: D[c(256)][m(128)] = sum_n hB[c][n]*eT[m][n] over K=4096
// epilogue: out = gamma * D / colsum[m] + x
// grid: (NN/128 [m], CC/256, BATCH)
// ---------------------------------------------------------------------------
__global__ __launch_bounds__(256, 1)
void attn_mma(const __nv_bfloat16* __restrict__ hB, const __nv_bfloat16* __restrict__ eT,
              const float* __restrict__ colsum,
              const float* __restrict__ x, const float* __restrict__ gamma_p,
              float* __restrict__ out)
{
    extern __shared__ char dsm[];
    const int b = blockIdx.z, c0 = blockIdx.y * 256, m0 = blockIdx.x * 128;
    const int lane = threadIdx.x & 31, wid = threadIdx.x >> 5;
    const int wm = (wid & 3) * 64, wn = (wid >> 2) * 64;

    float acc[4][8][4] = {};
    gemm_core(hB + ((size_t)b * CC + c0) * NN, NN,
              eT + ((size_t)b * NN + m0) * NN, NN, NN / 32, acc, dsm);

    const float gamma = *gamma_p;

    // per-thread scale (gamma / colsum) for the 16 m-columns this thread owns
    float inv[8][2];
    #pragma unroll
    for (int nt = 0; nt < 8; nt++) {
        int m = m0 + wn + nt * 8 + (lane & 3) * 2;
        inv[nt][0] = gamma / colsum[b * NN + m];
        inv[nt][1] = gamma / colsum[b * NN + m + 1];
    }

    #pragma unroll
    for (int mt = 0; mt < 4; mt++) {
        #pragma unroll
        for (int half = 0; half < 2; half++) {
            int c = c0 + wm + mt * 16 + (lane >> 2) + half * 8;
            size_t rowb = ((size_t)b * CC + c) * NN;
            #pragma unroll
            for (int nt = 0; nt < 8; nt++) {
                int m = m0 + wn + nt * 8 + (lane & 3) * 2;
                float2 xv = *(const float2*)(x + rowb + m);
                float2 ov;
                ov.x = acc[mt][nt][half * 2]     * inv[nt][0] + xv.x;
                ov.y = acc[mt][nt][half * 2 + 1] * inv[nt][1] + xv.y;
                *(float2*)(out + rowb + m) = ov;
            }
        }
    }
}

// ---------------------------------------------------------------------------
extern "C" void kernel_launch(void* const* d_in, const int* in_sizes, int n_in,
                              void* d_out, int out_size)
{
    const float* x     = (const float*)d_in[0];
    const float* f_w   = (const float*)d_in[1];
    const float* f_b   = (const float*)d_in[2];
    const float* g_w   = (const float*)d_in[3];
    const float* g_b   = (const float*)d_in[4];
    const float* h_w   = (const float*)d_in[5];
    const float* h_b   = (const float*)d_in[6];
    const float* gamma = (const float*)d_in[7];
    float* out = (float*)d_out;

    __nv_bfloat16 *pxT, *pfgw, *phw, *pfT, *pgT, *phB, *peT;
    float *psum;
    cudaGetSymbolAddress((void**)&pxT,  d_xT);
    cudaGetSymbolAddress((void**)&pfgw, d_fgw);
    cudaGetSymbolAddress((void**)&phw,  d_hw);
    cudaGetSymbolAddress((void**)&pfT,  d_fT);
    cudaGetSymbolAddress((void**)&pgT,  d_gT);
    cudaGetSymbolAddress((void**)&phB,  d_hB);
    cudaGetSymbolAddress((void**)&peT,  d_eT);
    cudaGetSymbolAddress((void**)&psum, d_colsum);

    // unconditional every call — deterministic, no static guards
    cudaFuncSetAttribute(fg_proj_mma, cudaFuncAttributeMaxDynamicSharedMemorySize, SMEM_DYN);
    cudaFuncSetAttribute(h_proj_mma,  cudaFuncAttributeMaxDynamicSharedMemorySize, SMEM_DYN);
    cudaFuncSetAttribute(scores_mma,  cudaFuncAttributeMaxDynamicSharedMemorySize, SMEM_DYN);
    cudaFuncSetAttribute(attn_mma,    cudaFuncAttributeMaxDynamicSharedMemorySize, SMEM_DYN);

    // prep (also zeroes colsum each call; pads fgw rows 128..255)
    conv_w_kernel<<<1536, 256>>>(f_w, g_w, h_w, pfgw, phw, psum);
    transpose_x_kernel<<<dim3(NN / 32, CC / 32, BATCH), dim3(32, 8)>>>(x, pxT);

    // projections (mma.sync, 256x128 tiles)
    fg_proj_mma<<<dim3(NN / 128, 1, BATCH), 256, SMEM_DYN>>>(pfgw, pxT, f_b, g_b, pfT, pgT);
    h_proj_mma <<<dim3(NN / 128, CC / 256, BATCH), 256, SMEM_DYN>>>(phw, pxT, h_b, phB);

    // scores -> exp -> transposed bf16 + column sums (fused)
    scores_mma<<<dim3(NN / 128, NN / 256, BATCH), 256, SMEM_DYN>>>(pfT, pgT, peT, psum);

    // attention GEMM + normalize-in-epilogue
    attn_mma<<<dim3(NN / 128, CC / 256, BATCH), 256, SMEM_DYN>>>(
        phB, peT, psum, x, gamma, out);
}

// round 13
// speedup vs baseline: 1.2430x; 1.2430x over previous
#include <cuda_runtime.h>
#include <cuda_bf16.h>
#include <cstdint>
#include <cstddef>

#define BATCH 4
#define CC    512
#define OO    64
#define NN    4096

// ---------------- scratch (device globals; allocation-free) ----------------
__device__ __nv_bfloat16 d_xT [BATCH * NN * CC];      // x transposed [b][n][k] bf16
__device__ __nv_bfloat16 d_fgw[128 * CC];             // stacked [f_w; g_w] bf16
__device__ __nv_bfloat16 d_hw [CC * CC];              // h_w bf16
__device__ __nv_bfloat16 d_fT [BATCH * NN * OO];      // f transposed [b][i][o]
__device__ __nv_bfloat16 d_gT [BATCH * NN * OO];      // g transposed [b][j][o]
__device__ __nv_bfloat16 d_hB [BATCH * CC * NN];      // h bf16 [b][c][n]
__device__ __nv_bfloat16 d_eT [(size_t)BATCH * NN * NN]; // exp(scores)^T [b][m][n] bf16
__device__ float d_colsum[BATCH * NN];                // sum_n exp(scores[n][m])

// ------------------------- helpers -----------------------------------------
__device__ __forceinline__ uint32_t smem_u32(const void* p) {
    uint32_t a;
    asm("{ .reg .u64 t; cvta.to.shared.u64 t, %1; cvt.u32.u64 %0, t; }"
        : "=r"(a) : "l"(p));
    return a;
}
__device__ __forceinline__ void cpa16(uint32_t s, const void* g) {
    asm volatile("cp.async.cg.shared.global [%0], [%1], 16;" :: "r"(s), "l"(g));
}
#define CP_COMMIT() asm volatile("cp.async.commit_group;" ::: "memory")
#define CP_WAIT1()  asm volatile("cp.async.wait_group 1;" ::: "memory")

__device__ __forceinline__ void ldmx4(uint32_t& r0, uint32_t& r1, uint32_t& r2,
                                      uint32_t& r3, uint32_t addr) {
    asm volatile("ldmatrix.sync.aligned.m8n8.x4.shared.b16 {%0,%1,%2,%3}, [%4];"
                 : "=r"(r0), "=r"(r1), "=r"(r2), "=r"(r3) : "r"(addr));
}
__device__ __forceinline__ void mma16816(float c[4], const uint32_t a[4],
                                         const uint32_t b[2]) {
    asm volatile(
        "mma.sync.aligned.m16n8k16.row.col.f32.bf16.bf16.f32 "
        "{%0,%1,%2,%3}, {%4,%5,%6,%7}, {%8,%9}, {%0,%1,%2,%3};"
        : "+f"(c[0]), "+f"(c[1]), "+f"(c[2]), "+f"(c[3])
        : "r"(a[0]), "r"(a[1]), "r"(a[2]), "r"(a[3]), "r"(b[0]), "r"(b[1]));
}

// smem tile: 128 rows x 64 bf16 (BK=64), pitch 72 elems = 144 B = 16*9:
//  - every (row, 8-elem col) address is 16B-aligned (144 % 16 == 0)
//  - bank group of row r, chunk c = (9r + c) mod 8 -> distinct over 8 ldmatrix
//    rows: conflict-free, no swizzle needed
#define TPITCH 72
#define TBYTES (128 * TPITCH * 2)          // 18432
#define NSTAGE 3
#define STAGE_BYTES (2 * TBYTES)           // 36864
#define SMEM_DYN (NSTAGE * STAGE_BYTES)    // 110592 -> 2 CTAs/SM (matches reg limit)

// Core GEMM: acc[mt][nt][4] += A[128 x K] * B[128 x K]^T, both K-major, BK=64.
// 3-stage cp.async circular pipeline, ONE __syncthreads per chunk.
__device__ __forceinline__ void gemm_core(
    const __nv_bfloat16* __restrict__ A, int lda,
    const __nv_bfloat16* __restrict__ B, int ldb,
    int nk, float acc[4][4][4], char* smem)
{
    const int tid = threadIdx.x;
    const int lane = tid & 31, wid = tid >> 5;
    const int wm = (wid >> 2) * 64, wn = (wid & 3) * 32;
    const uint32_t sbase = smem_u32(smem);

    auto issue = [&](int st) {
        if (st < nk) {
            uint32_t sA = sbase + (st % NSTAGE) * STAGE_BYTES;
            uint32_t sB = sA + TBYTES;
            #pragma unroll
            for (int p = 0; p < 8; p++) {
                int idx = tid + p * 256;            // 0..2047
                if (idx < 1024) {                   // A: 128 rows x 8 chunks
                    int row = idx >> 3, c = idx & 7;
                    cpa16(sA + (row * TPITCH + c * 8) * 2,
                          A + (size_t)row * lda + st * 64 + c * 8);
                } else {                            // B: 128 rows x 8 chunks
                    int i2 = idx - 1024;
                    int row = i2 >> 3, c = i2 & 7;
                    cpa16(sB + (row * TPITCH + c * 8) * 2,
                          B + (size_t)row * ldb + st * 64 + c * 8);
                }
            }
        }
        CP_COMMIT();
    };

    issue(0); issue(1);
    for (int k0 = 0; k0 < nk; k0++) {
        CP_WAIT1();
        __syncthreads();
        issue(k0 + 2);

        uint32_t sA = sbase + (k0 % NSTAGE) * STAGE_BYTES;
        uint32_t sB = sA + TBYTES;
        #pragma unroll
        for (int ks = 0; ks < 4; ks++) {
            uint32_t afr[4][4];
            #pragma unroll
            for (int mt = 0; mt < 4; mt++) {
                int row = wm + mt * 16 + (lane & 15);
                int col = ks * 16 + ((lane >> 4) & 1) * 8;
                ldmx4(afr[mt][0], afr[mt][1], afr[mt][2], afr[mt][3],
                      sA + (row * TPITCH + col) * 2);
            }
            uint32_t bfr[4][2];
            #pragma unroll
            for (int np = 0; np < 2; np++) {
                int row = wn + np * 16 + (lane & 7) + ((lane >> 4) & 1) * 8;
                int col = ks * 16 + ((lane >> 3) & 1) * 8;
                uint32_t r0, r1, r2, r3;
                ldmx4(r0, r1, r2, r3, sB + (row * TPITCH + col) * 2);
                bfr[np * 2][0] = r0; bfr[np * 2][1] = r1;
                bfr[np * 2 + 1][0] = r2; bfr[np * 2 + 1][1] = r3;
            }
            #pragma unroll
            for (int mt = 0; mt < 4; mt++)
                #pragma unroll
                for (int nt = 0; nt < 4; nt++)
                    mma16816(acc[mt][nt], afr[mt], bfr[nt]);
        }
    }
}

// ---------------------------------------------------------------------------
// prep: convert weights to bf16 (stacked fg + h) + zero colsum (every call)
// ---------------------------------------------------------------------------
__global__ __launch_bounds__(256)
void conv_w_kernel(const float* __restrict__ fw, const float* __restrict__ gw,
                   const float* __restrict__ hw,
                   __nv_bfloat16* __restrict__ fgw, __nv_bfloat16* __restrict__ hwb,
                   float* __restrict__ colsum)
{
    int i = blockIdx.x * 256 + threadIdx.x;
    if (i < BATCH * NN) colsum[i] = 0.0f;
    if (i < 128 * CC) {
        float v = (i < 64 * CC) ? fw[i] : gw[i - 64 * CC];
        fgw[i] = __float2bfloat16(v);
    }
    int j = i - 128 * CC;
    if (j >= 0 && j < CC * CC) hwb[j] = __float2bfloat16(hw[j]);
}

// ---------------------------------------------------------------------------
// prep: transpose x [b][k][n] fp32 -> xT [b][n][k] bf16
// ---------------------------------------------------------------------------
__global__ __launch_bounds__(256)
void transpose_x_kernel(const float* __restrict__ x, __nv_bfloat16* __restrict__ xT)
{
    __shared__ float t[32][33];
    const int b = blockIdx.z;
    const int n0 = blockIdx.x * 32, k0 = blockIdx.y * 32;
    const float* xb = x + (size_t)b * CC * NN;
    for (int r = threadIdx.y; r < 32; r += 8)
        t[r][threadIdx.x] = xb[(size_t)(k0 + r) * NN + n0 + threadIdx.x];
    __syncthreads();
    __nv_bfloat16* xo = xT + (size_t)b * NN * CC;
    for (int r = threadIdx.y; r < 32; r += 8)
        xo[(size_t)(n0 + r) * CC + k0 + threadIdx.x] = __float2bfloat16(t[threadIdx.x][r]);
}

// ---------------------------------------------------------------------------
// fg projection: D[o(128 stacked)][n(128)] over K=512; write fT/gT [n][o] bf16
// ---------------------------------------------------------------------------
__global__ __launch_bounds__(256)
void fg_proj_mma(const __nv_bfloat16* __restrict__ fgw, const __nv_bfloat16* __restrict__ xT,
                 const float* __restrict__ f_b, const float* __restrict__ g_b,
                 __nv_bfloat16* __restrict__ fT, __nv_bfloat16* __restrict__ gT)
{
    extern __shared__ char dsm[];
    const int b = blockIdx.z, n0 = blockIdx.x * 128;
    const int lane = threadIdx.x & 31, wid = threadIdx.x >> 5;
    const int wm = (wid >> 2) * 64, wn = (wid & 3) * 32;

    float acc[4][4][4] = {};
    gemm_core(fgw, CC, xT + (size_t)(b * NN + n0) * CC, CC, CC / 64, acc, dsm);

    __nv_bfloat16* fTb = fT + (size_t)b * NN * OO;
    __nv_bfloat16* gTb = gT + (size_t)b * NN * OO;
    #pragma unroll
    for (int mt = 0; mt < 4; mt++) {
        #pragma unroll
        for (int half = 0; half < 2; half++) {
            int o = wm + mt * 16 + (lane >> 2) + half * 8;
            float bias = (o < 64) ? f_b[o] : g_b[o - 64];
            __nv_bfloat16* dst = (o < 64) ? (fTb + o) : (gTb + (o - 64));
            #pragma unroll
            for (int nt = 0; nt < 4; nt++) {
                int n = n0 + wn + nt * 8 + (lane & 3) * 2;
                dst[(size_t)n * OO]       = __float2bfloat16(acc[mt][nt][half * 2]     + bias);
                dst[(size_t)(n + 1) * OO] = __float2bfloat16(acc[mt][nt][half * 2 + 1] + bias);
            }
        }
    }
}

// ---------------------------------------------------------------------------
// h projection: D[c(128)][n(128)] over K=512; write hB [c][n] bf16
// ---------------------------------------------------------------------------
__global__ __launch_bounds__(256)
void h_proj_mma(const __nv_bfloat16* __restrict__ hwb, const __nv_bfloat16* __restrict__ xT,
                const float* __restrict__ h_b, __nv_bfloat16* __restrict__ hB)
{
    extern __shared__ char dsm[];
    const int b = blockIdx.z, c0 = blockIdx.y * 128, n0 = blockIdx.x * 128;
    const int lane = threadIdx.x & 31, wid = threadIdx.x >> 5;
    const int wm = (wid >> 2) * 64, wn = (wid & 3) * 32;

    float acc[4][4][4] = {};
    gemm_core(hwb + (size_t)c0 * CC, CC,
              xT + (size_t)(b * NN + n0) * CC, CC, CC / 64, acc, dsm);

    __nv_bfloat16* hb = hB + (size_t)b * CC * NN;
    #pragma unroll
    for (int mt = 0; mt < 4; mt++) {
        #pragma unroll
        for (int half = 0; half < 2; half++) {
            int c = c0 + wm + mt * 16 + (lane >> 2) + half * 8;
            float bias = h_b[c];
            #pragma unroll
            for (int nt = 0; nt < 4; nt++) {
                int n = n0 + wn + nt * 8 + (lane & 3) * 2;
                __nv_bfloat162 v;
                v.x = __float2bfloat16(acc[mt][nt][half * 2]     + bias);
                v.y = __float2bfloat16(acc[mt][nt][half * 2 + 1] + bias);
                *(__nv_bfloat162*)(hb + (size_t)c * NN + n) = v;
            }
        }
    }
}

// ---------------------------------------------------------------------------
// scores+exp+transpose: e[i][j] = exp(fT[i,:].gT[j,:]); write eT[j][i] bf16;
// atomically accumulate colsum[j] = sum_i e[i][j].
// grid: (NN/128 [j], NN/128 [i], BATCH)
// ---------------------------------------------------------------------------
#define SPITCH 136   // bf16 elems per smem row (272B, 16B aligned)

__global__ __launch_bounds__(256)
void scores_mma(const __nv_bfloat16* __restrict__ fT, const __nv_bfloat16* __restrict__ gT,
                __nv_bfloat16* __restrict__ eT, float* __restrict__ colsum)
{
    extern __shared__ char dsm[];
    const int b = blockIdx.z, i0 = blockIdx.y * 128, j0 = blockIdx.x * 128;
    const int tid = threadIdx.x;
    const int lane = tid & 31, wid = tid >> 5;
    const int wm = (wid >> 2) * 64, wn = (wid & 3) * 32;

    float acc[4][4][4] = {};
    gemm_core(fT + (size_t)(b * NN + i0) * OO, OO,
              gT + (size_t)(b * NN + j0) * OO, OO, OO / 64, acc, dsm);

    __syncthreads();   // done with pipeline smem; reuse as transpose buffer
    __nv_bfloat16* ts = (__nv_bfloat16*)dsm;   // [128][SPITCH]

    // exp + transposed store into smem: ts[j][i] = bf16(exp(score[i][j]))
    #pragma unroll
    for (int mt = 0; mt < 4; mt++) {
        #pragma unroll
        for (int half = 0; half < 2; half++) {
            int i = wm + mt * 16 + (lane >> 2) + half * 8;
            #pragma unroll
            for (int nt = 0; nt < 4; nt++) {
                int j = wn + nt * 8 + (lane & 3) * 2;
                ts[(size_t)j * SPITCH + i]       =
                    __float2bfloat16(__expf(acc[mt][nt][half * 2]));
                ts[(size_t)(j + 1) * SPITCH + i] =
                    __float2bfloat16(__expf(acc[mt][nt][half * 2 + 1]));
            }
        }
    }
    __syncthreads();

    // coalesced write: eT[b][j0+j][i0+i], row j = 128 bf16 = 16 x uint4
    __nv_bfloat16* eb = eT + (size_t)b * NN * NN + (size_t)j0 * NN + i0;
    #pragma unroll
    for (int p = 0; p < 8; p++) {
        int lin = tid + p * 256;
        int row = lin >> 4, u = lin & 15;
        uint4 v = *(const uint4*)(ts + (size_t)row * SPITCH + u * 8);
        *(uint4*)(eb + (size_t)row * NN + u * 8) = v;
    }

    // partial column sums: thread pair (j, half) sums 64 values
    {
        int j = tid >> 1, hf = tid & 1;
        const __nv_bfloat16* rowp = ts + (size_t)j * SPITCH + hf * 64;
        float s = 0.0f;
        #pragma unroll
        for (int u = 0; u < 8; u++) {
            uint4 v = *(const uint4*)(rowp + u * 8);
            const __nv_bfloat162* h2 = (const __nv_bfloat162*)&v;
            #pragma unroll
            for (int q = 0; q < 4; q++) {
                float2 f2 = __bfloat1622float2(h2[q]);
                s += f2.x + f2.y;
            }
        }
        s += __shfl_xor_sync(0xffffffff, s, 1);
        if (hf == 0) atomicAdd(&colsum[b * NN + j0 + j], s);
    }
}

// ---------------------------------------------------------------------------
// attn: D[c(128)][m(128)] = sum_n hB[c][n]*eT[m][n] over K=4096
// epilogue: out = gamma * D / colsum[m] + x
// ---------------------------------------------------------------------------
__global__ __launch_bounds__(256)
void attn_mma(const __nv_bfloat16* __restrict__ hB, const __nv_bfloat16* __restrict__ eT,
              const float* __restrict__ colsum,
              const float* __restrict__ x, const float* __restrict__ gamma_p,
              float* __restrict__ out)
{
    extern __shared__ char dsm[];
    const int b = blockIdx.z, c0 = blockIdx.y * 128, m0 = blockIdx.x * 128;
    const int lane = threadIdx.x & 31, wid = threadIdx.x >> 5;
    const int wm = (wid >> 2) * 64, wn = (wid & 3) * 32;

    float acc[4][4][4] = {};
    gemm_core(hB + ((size_t)b * CC + c0) * NN, NN,
              eT + ((size_t)b * NN + m0) * NN, NN, NN / 64, acc, dsm);

    const float gamma = *gamma_p;

    // per-thread inverse sums for the 8 m-columns this thread owns
    float inv[4][2];
    #pragma unroll
    for (int nt = 0; nt < 4; nt++) {
        int m = m0 + wn + nt * 8 + (lane & 3) * 2;
        inv[nt][0] = gamma / colsum[b * NN + m];
        inv[nt][1] = gamma / colsum[b * NN + m + 1];
    }

    #pragma unroll
    for (int mt = 0; mt < 4; mt++) {
        #pragma unroll
        for (int half = 0; half < 2; half++) {
            int c = c0 + wm + mt * 16 + (lane >> 2) + half * 8;
            size_t rowb = ((size_t)b * CC + c) * NN;
            #pragma unroll
            for (int nt = 0; nt < 4; nt++) {
                int m = m0 + wn + nt * 8 + (lane & 3) * 2;
                float2 xv = *(const float2*)(x + rowb + m);
                float2 ov;
                ov.x = acc[mt][nt][half * 2]     * inv[nt][0] + xv.x;
                ov.y = acc[mt][nt][half * 2 + 1] * inv[nt][1] + xv.y;
                *(float2*)(out + rowb + m) = ov;
            }
        }
    }
}

// ---------------------------------------------------------------------------
extern "C" void kernel_launch(void* const* d_in, const int* in_sizes, int n_in,
                              void* d_out, int out_size)
{
    const float* x     = (const float*)d_in[0];
    const float* f_w   = (const float*)d_in[1];
    const float* f_b   = (const float*)d_in[2];
    const float* g_w   = (const float*)d_in[3];
    const float* g_b   = (const float*)d_in[4];
    const float* h_w   = (const float*)d_in[5];
    const float* h_b   = (const float*)d_in[6];
    const float* gamma = (const float*)d_in[7];
    float* out = (float*)d_out;

    __nv_bfloat16 *pxT, *pfgw, *phw, *pfT, *pgT, *phB, *peT;
    float *psum;
    cudaGetSymbolAddress((void**)&pxT,  d_xT);
    cudaGetSymbolAddress((void**)&pfgw, d_fgw);
    cudaGetSymbolAddress((void**)&phw,  d_hw);
    cudaGetSymbolAddress((void**)&pfT,  d_fT);
    cudaGetSymbolAddress((void**)&pgT,  d_gT);
    cudaGetSymbolAddress((void**)&phB,  d_hB);
    cudaGetSymbolAddress((void**)&peT,  d_eT);
    cudaGetSymbolAddress((void**)&psum, d_colsum);

    // unconditional every call — deterministic, no static guards
    cudaFuncSetAttribute(fg_proj_mma, cudaFuncAttributeMaxDynamicSharedMemorySize, SMEM_DYN);
    cudaFuncSetAttribute(h_proj_mma,  cudaFuncAttributeMaxDynamicSharedMemorySize, SMEM_DYN);
    cudaFuncSetAttribute(scores_mma,  cudaFuncAttributeMaxDynamicSharedMemorySize, SMEM_DYN);
    cudaFuncSetAttribute(attn_mma,    cudaFuncAttributeMaxDynamicSharedMemorySize, SMEM_DYN);

    // prep (also zeroes colsum each call)
    conv_w_kernel<<<1280, 256>>>(f_w, g_w, h_w, pfgw, phw, psum);
    transpose_x_kernel<<<dim3(NN / 32, CC / 32, BATCH), dim3(32, 8)>>>(x, pxT);

    // projections (mma.sync, BK=64)
    fg_proj_mma<<<dim3(NN / 128, 1, BATCH), 256, SMEM_DYN>>>(pfgw, pxT, f_b, g_b, pfT, pgT);
    h_proj_mma <<<dim3(NN / 128, CC / 128, BATCH), 256, SMEM_DYN>>>(phw, pxT, h_b, phB);

    // scores -> exp -> transposed bf16 + column sums (fused)
    scores_mma<<<dim3(NN / 128, NN / 128, BATCH), 256, SMEM_DYN>>>(pfT, pgT, peT, psum);

    // attention GEMM + normalize-in-epilogue
    attn_mma<<<dim3(NN / 128, CC / 128, BATCH), 256, SMEM_DYN>>>(
        phB, peT, psum, x, gamma, out);
}

// round 15
// speedup vs baseline: 1.2947x; 1.0416x over previous
#include <cuda_runtime.h>
#include <cuda_bf16.h>
#include <cstdint>
#include <cstddef>

#define BATCH 4
#define CC    512
#define OO    64
#define NN    4096

// ---------------- scratch (device globals; allocation-free) ----------------
__device__ __nv_bfloat16 d_xT [BATCH * NN * CC];      // x transposed [b][n][k] bf16
__device__ __nv_bfloat16 d_fgw[128 * CC];             // stacked [f_w; g_w] bf16
__device__ __nv_bfloat16 d_hw [CC * CC];              // h_w bf16
__device__ __nv_bfloat16 d_fT [BATCH * NN * OO];      // f transposed [b][i][o]
__device__ __nv_bfloat16 d_gT [BATCH * NN * OO];      // g transposed [b][j][o]
__device__ __nv_bfloat16 d_hB [BATCH * CC * NN];      // h bf16 [b][c][n]
__device__ __nv_bfloat16 d_eT [(size_t)BATCH * NN * NN]; // exp(scores)^T [b][m][n] bf16
__device__ float d_colsum[BATCH * NN];                // sum_n exp(scores[n][m])

// ------------------------- helpers -----------------------------------------
__device__ __forceinline__ uint32_t smem_u32(const void* p) {
    uint32_t a;
    asm("{ .reg .u64 t; cvta.to.shared.u64 t, %1; cvt.u32.u64 %0, t; }"
        : "=r"(a) : "l"(p));
    return a;
}
__device__ __forceinline__ void cpa16(uint32_t s, const void* g) {
    asm volatile("cp.async.cg.shared.global [%0], [%1], 16;" :: "r"(s), "l"(g));
}
#define CP_COMMIT() asm volatile("cp.async.commit_group;" ::: "memory")
#define CP_WAIT1()  asm volatile("cp.async.wait_group 1;" ::: "memory")

__device__ __forceinline__ void ldmx4(uint32_t& r0, uint32_t& r1, uint32_t& r2,
                                      uint32_t& r3, uint32_t addr) {
    asm volatile("ldmatrix.sync.aligned.m8n8.x4.shared.b16 {%0,%1,%2,%3}, [%4];"
                 : "=r"(r0), "=r"(r1), "=r"(r2), "=r"(r3) : "r"(addr));
}
__device__ __forceinline__ void mma16816(float c[4], const uint32_t a[4],
                                         const uint32_t b[2]) {
    asm volatile(
        "mma.sync.aligned.m16n8k16.row.col.f32.bf16.bf16.f32 "
        "{%0,%1,%2,%3}, {%4,%5,%6,%7}, {%8,%9}, {%0,%1,%2,%3};"
        : "+f"(c[0]), "+f"(c[1]), "+f"(c[2]), "+f"(c[3])
        : "r"(a[0]), "r"(a[1]), "r"(a[2]), "r"(a[3]), "r"(b[0]), "r"(b[1]));
}

// smem tile: 128 rows x 64 bf16 (BK=64), pitch 72 elems = 144 B = 16*9:
//  - every (row, 8-elem col) address is 16B-aligned (144 % 16 == 0)
//  - bank group of row r, chunk c = (9r + c) mod 8 -> distinct over 8 ldmatrix
//    rows: conflict-free, no swizzle needed
#define TPITCH 72
#define TBYTES (128 * TPITCH * 2)          // 18432
#define NSTAGE 3
#define STAGE_BYTES (2 * TBYTES)           // 36864
#define SMEM_DYN (NSTAGE * STAGE_BYTES)    // 110592 -> 2 CTAs/SM

#define NTHR 512                           // 16 warps: 4(m) x 4(n), warp tile 32x32

// Core GEMM: acc[mt][nt][4] += A[128 x K] * B[128 x K]^T, both K-major, BK=64.
// 512 threads, 16 warps of 32x32. 3-stage cp.async pipeline, ONE sync per chunk.
__device__ __forceinline__ void gemm_core(
    const __nv_bfloat16* __restrict__ A, int lda,
    const __nv_bfloat16* __restrict__ B, int ldb,
    int nk, float acc[2][4][4], char* smem)
{
    const int tid = threadIdx.x;
    const int lane = tid & 31, wid = tid >> 5;          // wid 0..15
    const int wm = (wid >> 2) * 32, wn = (wid & 3) * 32;
    const uint32_t sbase = smem_u32(smem);

    auto issue = [&](int st) {
        if (st < nk) {
            uint32_t sA = sbase + (st % NSTAGE) * STAGE_BYTES;
            uint32_t sB = sA + TBYTES;
            #pragma unroll
            for (int p = 0; p < 4; p++) {
                int idx = tid + p * NTHR;           // 0..2047
                if (idx < 1024) {                   // A: 128 rows x 8 chunks
                    int row = idx >> 3, c = idx & 7;
                    cpa16(sA + (row * TPITCH + c * 8) * 2,
                          A + (size_t)row * lda + st * 64 + c * 8);
                } else {                            // B: 128 rows x 8 chunks
                    int i2 = idx - 1024;
                    int row = i2 >> 3, c = i2 & 7;
                    cpa16(sB + (row * TPITCH + c * 8) * 2,
                          B + (size_t)row * ldb + st * 64 + c * 8);
                }
            }
        }
        CP_COMMIT();
    };

    issue(0); issue(1);
    for (int k0 = 0; k0 < nk; k0++) {
        CP_WAIT1();
        __syncthreads();
        issue(k0 + 2);

        uint32_t sA = sbase + (k0 % NSTAGE) * STAGE_BYTES;
        uint32_t sB = sA + TBYTES;
        #pragma unroll
        for (int ks = 0; ks < 4; ks++) {
            uint32_t afr[2][4];
            #pragma unroll
            for (int mt = 0; mt < 2; mt++) {
                int row = wm + mt * 16 + (lane & 15);
                int col = ks * 16 + ((lane >> 4) & 1) * 8;
                ldmx4(afr[mt][0], afr[mt][1], afr[mt][2], afr[mt][3],
                      sA + (row * TPITCH + col) * 2);
            }
            uint32_t bfr[4][2];
            #pragma unroll
            for (int np = 0; np < 2; np++) {
                int row = wn + np * 16 + (lane & 7) + ((lane >> 4) & 1) * 8;
                int col = ks * 16 + ((lane >> 3) & 1) * 8;
                uint32_t r0, r1, r2, r3;
                ldmx4(r0, r1, r2, r3, sB + (row * TPITCH + col) * 2);
                bfr[np * 2][0] = r0; bfr[np * 2][1] = r1;
                bfr[np * 2 + 1][0] = r2; bfr[np * 2 + 1][1] = r3;
            }
            #pragma unroll
            for (int mt = 0; mt < 2; mt++)
                #pragma unroll
                for (int nt = 0; nt < 4; nt++)
                    mma16816(acc[mt][nt], afr[mt], bfr[nt]);
        }
    }
}

// ---------------------------------------------------------------------------
// prep: convert weights to bf16 (stacked fg + h) + zero colsum (every call)
// ---------------------------------------------------------------------------
__global__ __launch_bounds__(256)
void conv_w_kernel(const float* __restrict__ fw, const float* __restrict__ gw,
                   const float* __restrict__ hw,
                   __nv_bfloat16* __restrict__ fgw, __nv_bfloat16* __restrict__ hwb,
                   float* __restrict__ colsum)
{
    int i = blockIdx.x * 256 + threadIdx.x;
    if (i < BATCH * NN) colsum[i] = 0.0f;
    if (i < 128 * CC) {
        float v = (i < 64 * CC) ? fw[i] : gw[i - 64 * CC];
        fgw[i] = __float2bfloat16(v);
    }
    int j = i - 128 * CC;
    if (j >= 0 && j < CC * CC) hwb[j] = __float2bfloat16(hw[j]);
}

// ---------------------------------------------------------------------------
// prep: transpose x [b][k][n] fp32 -> xT [b][n][k] bf16
// ---------------------------------------------------------------------------
__global__ __launch_bounds__(256)
void transpose_x_kernel(const float* __restrict__ x, __nv_bfloat16* __restrict__ xT)
{
    __shared__ float t[32][33];
    const int b = blockIdx.z;
    const int n0 = blockIdx.x * 32, k0 = blockIdx.y * 32;
    const float* xb = x + (size_t)b * CC * NN;
    for (int r = threadIdx.y; r < 32; r += 8)
        t[r][threadIdx.x] = xb[(size_t)(k0 + r) * NN + n0 + threadIdx.x];
    __syncthreads();
    __nv_bfloat16* xo = xT + (size_t)b * NN * CC;
    for (int r = threadIdx.y; r < 32; r += 8)
        xo[(size_t)(n0 + r) * CC + k0 + threadIdx.x] = __float2bfloat16(t[threadIdx.x][r]);
}

// ---------------------------------------------------------------------------
// fg projection: D[o(128 stacked)][n(128)] over K=512; write fT/gT [n][o] bf16
// ---------------------------------------------------------------------------
__global__ __launch_bounds__(NTHR, 2)
void fg_proj_mma(const __nv_bfloat16* __restrict__ fgw, const __nv_bfloat16* __restrict__ xT,
                 const float* __restrict__ f_b, const float* __restrict__ g_b,
                 __nv_bfloat16* __restrict__ fT, __nv_bfloat16* __restrict__ gT)
{
    extern __shared__ char dsm[];
    const int b = blockIdx.z, n0 = blockIdx.x * 128;
    const int lane = threadIdx.x & 31, wid = threadIdx.x >> 5;
    const int wm = (wid >> 2) * 32, wn = (wid & 3) * 32;

    float acc[2][4][4] = {};
    gemm_core(fgw, CC, xT + (size_t)(b * NN + n0) * CC, CC, CC / 64, acc, dsm);

    __nv_bfloat16* fTb = fT + (size_t)b * NN * OO;
    __nv_bfloat16* gTb = gT + (size_t)b * NN * OO;
    #pragma unroll
    for (int mt = 0; mt < 2; mt++) {
        #pragma unroll
        for (int half = 0; half < 2; half++) {
            int o = wm + mt * 16 + (lane >> 2) + half * 8;
            float bias = (o < 64) ? f_b[o] : g_b[o - 64];
            __nv_bfloat16* dst = (o < 64) ? (fTb + o) : (gTb + (o - 64));
            #pragma unroll
            for (int nt = 0; nt < 4; nt++) {
                int n = n0 + wn + nt * 8 + (lane & 3) * 2;
                dst[(size_t)n * OO]       = __float2bfloat16(acc[mt][nt][half * 2]     + bias);
                dst[(size_t)(n + 1) * OO] = __float2bfloat16(acc[mt][nt][half * 2 + 1] + bias);
            }
        }
    }
}

// ---------------------------------------------------------------------------
// h projection: D[c(128)][n(128)] over K=512; write hB [c][n] bf16
// ---------------------------------------------------------------------------
__global__ __launch_bounds__(NTHR, 2)
void h_proj_mma(const __nv_bfloat16* __restrict__ hwb, const __nv_bfloat16* __restrict__ xT,
                const float* __restrict__ h_b, __nv_bfloat16* __restrict__ hB)
{
    extern __shared__ char dsm[];
    const int b = blockIdx.z, c0 = blockIdx.y * 128, n0 = blockIdx.x * 128;
    const int lane = threadIdx.x & 31, wid = threadIdx.x >> 5;
    const int wm = (wid >> 2) * 32, wn = (wid & 3) * 32;

    float acc[2][4][4] = {};
    gemm_core(hwb + (size_t)c0 * CC, CC,
              xT + (size_t)(b * NN + n0) * CC, CC, CC / 64, acc, dsm);

    __nv_bfloat16* hb = hB + (size_t)b * CC * NN;
    #pragma unroll
    for (int mt = 0; mt < 2; mt++) {
        #pragma unroll
        for (int half = 0; half < 2; half++) {
            int c = c0 + wm + mt * 16 + (lane >> 2) + half * 8;
            float bias = h_b[c];
            #pragma unroll
            for (int nt = 0; nt < 4; nt++) {
                int n = n0 + wn + nt * 8 + (lane & 3) * 2;
                __nv_bfloat162 v;
                v.x = __float2bfloat16(acc[mt][nt][half * 2]     + bias);
                v.y = __float2bfloat16(acc[mt][nt][half * 2 + 1] + bias);
                *(__nv_bfloat162*)(hb + (size_t)c * NN + n) = v;
            }
        }
    }
}

// ---------------------------------------------------------------------------
// scores+exp+transpose: e[i][j] = exp(fT[i,:].gT[j,:]); write eT[j][i] bf16;
// atomically accumulate colsum[j] = sum_i e[i][j].
// grid: (NN/128 [j], NN/128 [i], BATCH)
// ---------------------------------------------------------------------------
#define SPITCH 136   // bf16 elems per smem row (272B, 16B aligned)

__global__ __launch_bounds__(NTHR, 2)
void scores_mma(const __nv_bfloat16* __restrict__ fT, const __nv_bfloat16* __restrict__ gT,
                __nv_bfloat16* __restrict__ eT, float* __restrict__ colsum)
{
    extern __shared__ char dsm[];
    const int b = blockIdx.z, i0 = blockIdx.y * 128, j0 = blockIdx.x * 128;
    const int tid = threadIdx.x;
    const int lane = tid & 31, wid = tid >> 5;
    const int wm = (wid >> 2) * 32, wn = (wid & 3) * 32;

    float acc[2][4][4] = {};
    gemm_core(fT + (size_t)(b * NN + i0) * OO, OO,
              gT + (size_t)(b * NN + j0) * OO, OO, OO / 64, acc, dsm);

    __syncthreads();   // done with pipeline smem; reuse as transpose buffer
    __nv_bfloat16* ts = (__nv_bfloat16*)dsm;   // [128][SPITCH]

    // exp + transposed store into smem: ts[j][i] = bf16(exp(score[i][j]))
    #pragma unroll
    for (int mt = 0; mt < 2; mt++) {
        #pragma unroll
        for (int half = 0; half < 2; half++) {
            int i = wm + mt * 16 + (lane >> 2) + half * 8;
            #pragma unroll
            for (int nt = 0; nt < 4; nt++) {
                int j = wn + nt * 8 + (lane & 3) * 2;
                ts[(size_t)j * SPITCH + i]       =
                    __float2bfloat16(__expf(acc[mt][nt][half * 2]));
                ts[(size_t)(j + 1) * SPITCH + i] =
                    __float2bfloat16(__expf(acc[mt][nt][half * 2 + 1]));
            }
        }
    }
    __syncthreads();

    // coalesced write: eT[b][j0+j][i0+i], row j = 128 bf16 = 16 x uint4
    __nv_bfloat16* eb = eT + (size_t)b * NN * NN + (size_t)j0 * NN + i0;
    #pragma unroll
    for (int p = 0; p < 4; p++) {
        int lin = tid + p * NTHR;
        int row = lin >> 4, u = lin & 15;
        uint4 v = *(const uint4*)(ts + (size_t)row * SPITCH + u * 8);
        *(uint4*)(eb + (size_t)row * NN + u * 8) = v;
    }

    // partial column sums: 4 threads per j, 32 values each
    {
        int j = tid >> 2, q = tid & 3;
        const __nv_bfloat16* rowp = ts + (size_t)j * SPITCH + q * 32;
        float s = 0.0f;
        #pragma unroll
        for (int u = 0; u < 4; u++) {
            uint4 v = *(const uint4*)(rowp + u * 8);
            const __nv_bfloat162* h2 = (const __nv_bfloat162*)&v;
            #pragma unroll
            for (int w = 0; w < 4; w++) {
                float2 f2 = __bfloat1622float2(h2[w]);
                s += f2.x + f2.y;
            }
        }
        s += __shfl_xor_sync(0xffffffff, s, 1);
        s += __shfl_xor_sync(0xffffffff, s, 2);
        if (q == 0) atomicAdd(&colsum[b * NN + j0 + j], s);
    }
}

// ---------------------------------------------------------------------------
// attn: D[c(128)][m(128)] = sum_n hB[c][n]*eT[m][n] over K=4096
// epilogue: out = gamma * D / colsum[m] + x
// ---------------------------------------------------------------------------
__global__ __launch_bounds__(NTHR, 2)
void attn_mma(const __nv_bfloat16* __restrict__ hB, const __nv_bfloat16* __restrict__ eT,
              const float* __restrict__ colsum,
              const float* __restrict__ x, const float* __restrict__ gamma_p,
              float* __restrict__ out)
{
    extern __shared__ char dsm[];
    const int b = blockIdx.z, c0 = blockIdx.y * 128, m0 = blockIdx.x * 128;
    const int lane = threadIdx.x & 31, wid = threadIdx.x >> 5;
    const int wm = (wid >> 2) * 32, wn = (wid & 3) * 32;

    float acc[2][4][4] = {};
    gemm_core(hB + ((size_t)b * CC + c0) * NN, NN,
              eT + ((size_t)b * NN + m0) * NN, NN, NN / 64, acc, dsm);

    const float gamma = *gamma_p;

    // per-thread inverse sums for the 8 m-columns this thread owns
    float inv[4][2];
    #pragma unroll
    for (int nt = 0; nt < 4; nt++) {
        int m = m0 + wn + nt * 8 + (lane & 3) * 2;
        inv[nt][0] = gamma / colsum[b * NN + m];
        inv[nt][1] = gamma / colsum[b * NN + m + 1];
    }

    #pragma unroll
    for (int mt = 0; mt < 2; mt++) {
        #pragma unroll
        for (int half = 0; half < 2; half++) {
            int c = c0 + wm + mt * 16 + (lane >> 2) + half * 8;
            size_t rowb = ((size_t)b * CC + c) * NN;
            #pragma unroll
            for (int nt = 0; nt < 4; nt++) {
                int m = m0 + wn + nt * 8 + (lane & 3) * 2;
                float2 xv = *(const float2*)(x + rowb + m);
                float2 ov;
                ov.x = acc[mt][nt][half * 2]     * inv[nt][0] + xv.x;
                ov.y = acc[mt][nt][half * 2 + 1] * inv[nt][1] + xv.y;
                *(float2*)(out + rowb + m) = ov;
            }
        }
    }
}

// ---------------------------------------------------------------------------
extern "C" void kernel_launch(void* const* d_in, const int* in_sizes, int n_in,
                              void* d_out, int out_size)
{
    const float* x     = (const float*)d_in[0];
    const float* f_w   = (const float*)d_in[1];
    const float* f_b   = (const float*)d_in[2];
    const float* g_w   = (const float*)d_in[3];
    const float* g_b   = (const float*)d_in[4];
    const float* h_w   = (const float*)d_in[5];
    const float* h_b   = (const float*)d_in[6];
    const float* gamma = (const float*)d_in[7];
    float* out = (float*)d_out;

    __nv_bfloat16 *pxT, *pfgw, *phw, *pfT, *pgT, *phB, *peT;
    float *psum;
    cudaGetSymbolAddress((void**)&pxT,  d_xT);
    cudaGetSymbolAddress((void**)&pfgw, d_fgw);
    cudaGetSymbolAddress((void**)&phw,  d_hw);
    cudaGetSymbolAddress((void**)&pfT,  d_fT);
    cudaGetSymbolAddress((void**)&pgT,  d_gT);
    cudaGetSymbolAddress((void**)&phB,  d_hB);
    cudaGetSymbolAddress((void**)&peT,  d_eT);
    cudaGetSymbolAddress((void**)&psum, d_colsum);

    // unconditional every call — deterministic, no static guards
    cudaFuncSetAttribute(fg_proj_mma, cudaFuncAttributeMaxDynamicSharedMemorySize, SMEM_DYN);
    cudaFuncSetAttribute(h_proj_mma,  cudaFuncAttributeMaxDynamicSharedMemorySize, SMEM_DYN);
    cudaFuncSetAttribute(scores_mma,  cudaFuncAttributeMaxDynamicSharedMemorySize, SMEM_DYN);
    cudaFuncSetAttribute(attn_mma,    cudaFuncAttributeMaxDynamicSharedMemorySize, SMEM_DYN);

    // prep (also zeroes colsum each call)
    conv_w_kernel<<<1280, 256>>>(f_w, g_w, h_w, pfgw, phw, psum);
    transpose_x_kernel<<<dim3(NN / 32, CC / 32, BATCH), dim3(32, 8)>>>(x, pxT);

    // projections (mma.sync, BK=64, 512-thread CTAs)
    fg_proj_mma<<<dim3(NN / 128, 1, BATCH), NTHR, SMEM_DYN>>>(pfgw, pxT, f_b, g_b, pfT, pgT);
    h_proj_mma <<<dim3(NN / 128, CC / 128, BATCH), NTHR, SMEM_DYN>>>(phw, pxT, h_b, phB);

    // scores -> exp -> transposed bf16 + column sums (fused)
    scores_mma<<<dim3(NN / 128, NN / 128, BATCH), NTHR, SMEM_DYN>>>(pfT, pgT, peT, psum);

    // attention GEMM + normalize-in-epilogue
    attn_mma<<<dim3(NN / 128, CC / 128, BATCH), NTHR, SMEM_DYN>>>(
        phB, peT, psum, x, gamma, out);
}